// round 1
// baseline (speedup 1.0000x reference)
#include <cuda_runtime.h>
#include <math.h>

// ---------------- problem constants ----------------
#define BB 8192
#define DD 2048
#define HH 512
#define AA 3
#define EPS 1e-5f

#define ROWG 128
#define NG (BB / ROWG)   // 64

// ---------------- scratch (static device globals; no allocation) ------------
__device__ float g_big[BB * 2 * DD];      // hcat, later FFN mid
__device__ float g_h1[BB * HH];
__device__ float g_h2[BB * (HH / 2)];
__device__ float g_gf[BB * DD];           // gate -> gated features (in place)
__device__ float g_q[BB * DD];            // later reused for FFN output
__device__ float g_k1[BB * DD];
__device__ float g_k2[BB * DD];
__device__ float g_v1[BB * DD];
__device__ float g_v2[BB * DD];
__device__ float g_w1v[BB];
__device__ float g_gated[BB * DD];
__device__ float g_res1[BB * DD];
__device__ float g_norm[BB * DD];
__device__ float g_psum[NG * AA * DD];
__device__ float g_psq[NG * AA * DD];
__device__ float g_mean[AA * DD];
__device__ float g_istd[AA * DD];
__device__ int   g_cnt[AA];

// ---------------- helpers ----------------
__device__ __forceinline__ float gelu_f(float x) {
    return 0.5f * x * (1.0f + erff(x * 0.70710678118654752440f));
}

__device__ __forceinline__ void blockReduce2(float& a, float& b) {
    __shared__ float sa[32], sb[32];
    int lane = threadIdx.x & 31, wid = threadIdx.x >> 5;
    #pragma unroll
    for (int o = 16; o > 0; o >>= 1) {
        a += __shfl_xor_sync(0xffffffffu, a, o);
        b += __shfl_xor_sync(0xffffffffu, b, o);
    }
    if (lane == 0) { sa[wid] = a; sb[wid] = b; }
    __syncthreads();
    int nw = blockDim.x >> 5;
    if (wid == 0) {
        a = (lane < nw) ? sa[lane] : 0.f;
        b = (lane < nw) ? sb[lane] : 0.f;
        #pragma unroll
        for (int o = 16; o > 0; o >>= 1) {
            a += __shfl_xor_sync(0xffffffffu, a, o);
            b += __shfl_xor_sync(0xffffffffu, b, o);
        }
        if (lane == 0) { sa[0] = a; sb[0] = b; }
    }
    __syncthreads();
    a = sa[0]; b = sb[0];
}

// ---------------- SGEMM: C[M,N] = act(A[M,K] @ W[K,N] + bias) ----------------
#define BM 128
#define BN 128
#define BK 16
#define TM 8
#define TN 8
#define ACT_NONE 0
#define ACT_GELU 1
#define ACT_SIGMOID 2

__global__ __launch_bounds__(256, 2)
void sgemm_kernel(const float* __restrict__ A, const float* __restrict__ W,
                  const float* __restrict__ bias, float* __restrict__ C,
                  int M, int N, int K, int act) {
    __shared__ float As[BK][BM];
    __shared__ float Bs[BK][BN];
    int tid = threadIdx.x;
    int bx = blockIdx.x;   // N tile
    int by = blockIdx.y;   // M tile

    const float* Ab = A + (size_t)by * BM * K;
    const float* Wb = W + (size_t)bx * BN;

    int arow = tid >> 2;            // 0..63
    int acol = (tid & 3) * 4;       // 0,4,8,12
    int brow = tid >> 5;            // 0..7
    int bcol = (tid & 31) * 4;      // 0..124

    int ty = tid >> 4, tx = tid & 15;

    float acc[TM][TN];
    #pragma unroll
    for (int i = 0; i < TM; i++)
        #pragma unroll
        for (int j = 0; j < TN; j++) acc[i][j] = 0.f;

    for (int k0 = 0; k0 < K; k0 += BK) {
        #pragma unroll
        for (int i = 0; i < 2; i++) {
            int r = arow + i * 64;
            float4 a = *(const float4*)(Ab + (size_t)r * K + k0 + acol);
            As[acol + 0][r] = a.x; As[acol + 1][r] = a.y;
            As[acol + 2][r] = a.z; As[acol + 3][r] = a.w;
        }
        #pragma unroll
        for (int i = 0; i < 2; i++) {
            int r = brow + i * 8;
            *(float4*)(&Bs[r][bcol]) = *(const float4*)(Wb + (size_t)(k0 + r) * N + bcol);
        }
        __syncthreads();
        #pragma unroll
        for (int k = 0; k < BK; k++) {
            float ra[TM], rb[TN];
            #pragma unroll
            for (int i = 0; i < TM; i++) ra[i] = As[k][ty * TM + i];
            #pragma unroll
            for (int j = 0; j < TN; j++) rb[j] = Bs[k][tx * TN + j];
            #pragma unroll
            for (int i = 0; i < TM; i++)
                #pragma unroll
                for (int j = 0; j < TN; j++) acc[i][j] += ra[i] * rb[j];
        }
        __syncthreads();
    }

    int crow0 = by * BM + ty * TM;
    int ccol0 = bx * BN + tx * TN;
    #pragma unroll
    for (int i = 0; i < TM; i++) {
        #pragma unroll
        for (int j = 0; j < TN; j += 4) {
            float4 v;
            float* p = &v.x;
            #pragma unroll
            for (int jj = 0; jj < 4; jj++) {
                float c = acc[i][j + jj] + bias[ccol0 + j + jj];
                if (act == ACT_GELU) c = gelu_f(c);
                else if (act == ACT_SIGMOID) c = 1.f / (1.f + expf(-c));
                p[jj] = c;
            }
            *(float4*)(C + (size_t)(crow0 + i) * N + ccol0 + j) = v;
        }
    }
}

// ---------------- elementwise / rowwise kernels ----------------
__global__ void concat_kernel(const float* __restrict__ f1, const float* __restrict__ f2,
                              float* __restrict__ out) {
    int i4 = blockIdx.x * blockDim.x + threadIdx.x;   // over BB*4096/4
    int row = i4 >> 10;          // 1024 float4 per row
    int c4 = i4 & 1023;
    float4 v;
    if (c4 < 512) v = ((const float4*)f1)[(size_t)row * 512 + c4];
    else          v = ((const float4*)f2)[(size_t)row * 512 + (c4 - 512)];
    ((float4*)out)[i4] = v;
}

// in-place LN + GELU over rows of length N (blockDim = N/4)
__global__ void ln_gelu_kernel(float* __restrict__ x, const float* __restrict__ g,
                               const float* __restrict__ b, int N) {
    int row = blockIdx.x, t = threadIdx.x;
    float4* X = (float4*)(x + (size_t)row * N);
    float4 v = X[t];
    float s = v.x + v.y + v.z + v.w;
    float q = v.x * v.x + v.y * v.y + v.z * v.z + v.w * v.w;
    blockReduce2(s, q);
    float mu = s / N;
    float is = rsqrtf(q / N - mu * mu + EPS);
    float4 gv = ((const float4*)g)[t];
    float4 bv = ((const float4*)b)[t];
    v.x = gelu_f((v.x - mu) * is * gv.x + bv.x);
    v.y = gelu_f((v.y - mu) * is * gv.y + bv.y);
    v.z = gelu_f((v.z - mu) * is * gv.z + bv.z);
    v.w = gelu_f((v.w - mu) * is * gv.w + bv.w);
    X[t] = v;
}

__global__ void gate_combine_kernel(float* __restrict__ gate_gf,
                                    const float* __restrict__ f1,
                                    const float* __restrict__ f2) {
    int i = blockIdx.x * blockDim.x + threadIdx.x;   // over BB*DD/4
    float4 g = ((float4*)gate_gf)[i];
    float4 a = ((const float4*)f1)[i];
    float4 b = ((const float4*)f2)[i];
    float4 r;
    r.x = g.x * a.x + (1.f - g.x) * b.x;
    r.y = g.y * a.y + (1.f - g.y) * b.y;
    r.z = g.z * a.z + (1.f - g.z) * b.z;
    r.w = g.w * a.w + (1.f - g.w) * b.w;
    ((float4*)gate_gf)[i] = r;
}

__global__ void attn_score_kernel(const float* __restrict__ q, const float* __restrict__ k1,
                                  const float* __restrict__ k2, float* __restrict__ w1v) {
    int row = blockIdx.x, t = threadIdx.x;
    const float4* Q = (const float4*)(q + (size_t)row * DD);
    const float4* K1 = (const float4*)(k1 + (size_t)row * DD);
    const float4* K2 = (const float4*)(k2 + (size_t)row * DD);
    float s1 = 0.f, s2 = 0.f;
    #pragma unroll
    for (int j = 0; j < 2; j++) {
        int c = t + j * 256;
        float4 a = Q[c], b = K1[c], d = K2[c];
        s1 += a.x * b.x + a.y * b.y + a.z * b.z + a.w * b.w;
        s2 += a.x * d.x + a.y * d.y + a.z * d.z + a.w * d.w;
    }
    blockReduce2(s1, s2);
    if (t == 0) {
        float inv = 1.f / sqrtf((float)DD);
        s1 *= inv; s2 *= inv;
        float m = fmaxf(s1, s2);
        float e1 = expf(s1 - m), e2 = expf(s2 - m);
        w1v[row] = e1 / (e1 + e2);
    }
}

// gated = LN(gf + w1*v1 + (1-w1)*v2)
__global__ void attn_ln_kernel(const float* __restrict__ gf, const float* __restrict__ v1,
                               const float* __restrict__ v2, const float* __restrict__ w1v,
                               const float* __restrict__ g, const float* __restrict__ b,
                               float* __restrict__ out) {
    int row = blockIdx.x, t = threadIdx.x;
    const float4* GF = (const float4*)(gf + (size_t)row * DD);
    const float4* V1 = (const float4*)(v1 + (size_t)row * DD);
    const float4* V2 = (const float4*)(v2 + (size_t)row * DD);
    float w1 = w1v[row], w2 = 1.f - w1;
    float4 a[2];
    float s = 0.f, q = 0.f;
    #pragma unroll
    for (int j = 0; j < 2; j++) {
        int c = t + j * 256;
        float4 x = GF[c], y = V1[c], z = V2[c];
        float4 r;
        r.x = x.x + w1 * y.x + w2 * z.x;
        r.y = x.y + w1 * y.y + w2 * z.y;
        r.z = x.z + w1 * y.z + w2 * z.z;
        r.w = x.w + w1 * y.w + w2 * z.w;
        a[j] = r;
        s += r.x + r.y + r.z + r.w;
        q += r.x * r.x + r.y * r.y + r.z * r.z + r.w * r.w;
    }
    blockReduce2(s, q);
    float mu = s / DD;
    float is = rsqrtf(q / DD - mu * mu + EPS);
    #pragma unroll
    for (int j = 0; j < 2; j++) {
        int c = t + j * 256;
        float4 gv = ((const float4*)g)[c];
        float4 bv = ((const float4*)b)[c];
        float4 r = a[j];
        r.x = (r.x - mu) * is * gv.x + bv.x;
        r.y = (r.y - mu) * is * gv.y + bv.y;
        r.z = (r.z - mu) * is * gv.z + bv.z;
        r.w = (r.w - mu) * is * gv.w + bv.w;
        ((float4*)(out + (size_t)row * DD))[c] = r;
    }
}

// out = LN(xa + xb)
__global__ void add_ln_kernel(const float* __restrict__ xa, const float* __restrict__ xb,
                              const float* __restrict__ g, const float* __restrict__ b,
                              float* __restrict__ out) {
    int row = blockIdx.x, t = threadIdx.x;
    const float4* XA = (const float4*)(xa + (size_t)row * DD);
    const float4* XB = (const float4*)(xb + (size_t)row * DD);
    float4 a[2];
    float s = 0.f, q = 0.f;
    #pragma unroll
    for (int j = 0; j < 2; j++) {
        int c = t + j * 256;
        float4 x = XA[c], y = XB[c];
        float4 r;
        r.x = x.x + y.x; r.y = x.y + y.y; r.z = x.z + y.z; r.w = x.w + y.w;
        a[j] = r;
        s += r.x + r.y + r.z + r.w;
        q += r.x * r.x + r.y * r.y + r.z * r.z + r.w * r.w;
    }
    blockReduce2(s, q);
    float mu = s / DD;
    float is = rsqrtf(q / DD - mu * mu + EPS);
    #pragma unroll
    for (int j = 0; j < 2; j++) {
        int c = t + j * 256;
        float4 gv = ((const float4*)g)[c];
        float4 bv = ((const float4*)b)[c];
        float4 r = a[j];
        r.x = (r.x - mu) * is * gv.x + bv.x;
        r.y = (r.y - mu) * is * gv.y + bv.y;
        r.z = (r.z - mu) * is * gv.z + bv.z;
        r.w = (r.w - mu) * is * gv.w + bv.w;
        ((float4*)(out + (size_t)row * DD))[c] = r;
    }
}

// ---------------- aspect BN (deterministic two-stage) ----------------
__global__ void bn_count_kernel(const int* __restrict__ ids) {
    __shared__ int c[AA];
    if (threadIdx.x < AA) c[threadIdx.x] = 0;
    __syncthreads();
    for (int i = threadIdx.x; i < BB; i += blockDim.x) atomicAdd(&c[ids[i]], 1);
    __syncthreads();
    if (threadIdx.x < AA) g_cnt[threadIdx.x] = c[threadIdx.x];
}

__global__ void bn_partial_kernel(const float* __restrict__ x, const int* __restrict__ ids) {
    int d = blockIdx.x * blockDim.x + threadIdx.x;   // column
    int g0 = blockIdx.y * ROWG;
    __shared__ int sid[ROWG];
    for (int i = threadIdx.x; i < ROWG; i += blockDim.x) sid[i] = ids[g0 + i];
    __syncthreads();
    float s0 = 0.f, s1 = 0.f, s2 = 0.f, q0 = 0.f, q1 = 0.f, q2 = 0.f;
    for (int r = 0; r < ROWG; r++) {
        float v = x[(size_t)(g0 + r) * DD + d];
        int a = sid[r];
        float vv = v * v;
        if (a == 0)      { s0 += v; q0 += vv; }
        else if (a == 1) { s1 += v; q1 += vv; }
        else             { s2 += v; q2 += vv; }
    }
    size_t base = (size_t)blockIdx.y * AA * DD + d;
    g_psum[base]          = s0; g_psq[base]          = q0;
    g_psum[base + DD]     = s1; g_psq[base + DD]     = q1;
    g_psum[base + 2 * DD] = s2; g_psq[base + 2 * DD] = q2;
}

__global__ void bn_finalize_kernel() {
    int i = blockIdx.x * blockDim.x + threadIdx.x;   // over AA*DD
    if (i >= AA * DD) return;
    float s = 0.f, q = 0.f;
    for (int g = 0; g < NG; g++) {
        s += g_psum[(size_t)g * AA * DD + i];
        q += g_psq[(size_t)g * AA * DD + i];
    }
    int a = i / DD;
    float safe = fmaxf((float)g_cnt[a], 1.f);
    float m = s / safe;
    float var = q / safe - m * m;
    g_mean[i] = m;
    g_istd[i] = rsqrtf(var + EPS);
}

__global__ void bn_apply_kernel(const float* __restrict__ x, const int* __restrict__ ids,
                                const float* __restrict__ bng, const float* __restrict__ bnb,
                                float* __restrict__ out) {
    int i4 = blockIdx.x * blockDim.x + threadIdx.x;  // over BB*DD/4
    int row = i4 / (DD / 4);
    int c4 = i4 % (DD / 4);
    int a = ids[row];
    float4 v = ((const float4*)x)[i4];
    if (g_cnt[a] > 1) {
        size_t off = (size_t)a * DD / 4 + c4;
        float4 m = ((const float4*)g_mean)[off];
        float4 is = ((const float4*)g_istd)[off];
        float4 gv = ((const float4*)bng)[off];
        float4 bv = ((const float4*)bnb)[off];
        v.x = (v.x - m.x) * is.x * gv.x + bv.x;
        v.y = (v.y - m.y) * is.y * gv.y + bv.y;
        v.z = (v.z - m.z) * is.z * gv.z + bv.z;
        v.w = (v.w - m.w) * is.w * gv.w + bv.w;
    }
    ((float4*)out)[i4] = v;
}

// ---------------- launch ----------------
static inline void sgemm(const float* A, const float* W, const float* bias, float* C,
                         int M, int N, int K, int act) {
    dim3 grid(N / BN, M / BM);
    sgemm_kernel<<<grid, 256>>>(A, W, bias, C, M, N, K, act);
}

extern "C" void kernel_launch(void* const* d_in, const int* in_sizes, int n_in,
                              void* d_out, int out_size) {
    const float* f1   = (const float*)d_in[0];
    const float* f2   = (const float*)d_in[1];
    const int*   ids  = (const int*)d_in[2];
    const float* gW1  = (const float*)d_in[3];
    const float* gb1  = (const float*)d_in[4];
    const float* gl1g = (const float*)d_in[5];
    const float* gl1b = (const float*)d_in[6];
    const float* gW2  = (const float*)d_in[7];
    const float* gb2  = (const float*)d_in[8];
    const float* gl2g = (const float*)d_in[9];
    const float* gl2b = (const float*)d_in[10];
    const float* gW3  = (const float*)d_in[11];
    const float* gb3  = (const float*)d_in[12];
    const float* qW   = (const float*)d_in[13];
    const float* qb   = (const float*)d_in[14];
    const float* kW   = (const float*)d_in[15];
    const float* kb   = (const float*)d_in[16];
    const float* vW   = (const float*)d_in[17];
    const float* vb   = (const float*)d_in[18];
    const float* alng = (const float*)d_in[19];
    const float* alnb = (const float*)d_in[20];
    const float* bng  = (const float*)d_in[21];
    const float* bnb  = (const float*)d_in[22];
    const float* ln1g = (const float*)d_in[23];
    const float* ln1b = (const float*)d_in[24];
    const float* fW1  = (const float*)d_in[25];
    const float* fb1  = (const float*)d_in[26];
    const float* fW2  = (const float*)d_in[27];
    const float* fb2  = (const float*)d_in[28];
    const float* ln2g = (const float*)d_in[29];
    const float* ln2b = (const float*)d_in[30];

    float *big, *h1, *h2, *gf, *q, *k1, *k2, *v1, *v2, *w1v, *gated, *res1, *norm;
    cudaGetSymbolAddress((void**)&big,  g_big);
    cudaGetSymbolAddress((void**)&h1,   g_h1);
    cudaGetSymbolAddress((void**)&h2,   g_h2);
    cudaGetSymbolAddress((void**)&gf,   g_gf);
    cudaGetSymbolAddress((void**)&q,    g_q);
    cudaGetSymbolAddress((void**)&k1,   g_k1);
    cudaGetSymbolAddress((void**)&k2,   g_k2);
    cudaGetSymbolAddress((void**)&v1,   g_v1);
    cudaGetSymbolAddress((void**)&v2,   g_v2);
    cudaGetSymbolAddress((void**)&w1v,  g_w1v);
    cudaGetSymbolAddress((void**)&gated, g_gated);
    cudaGetSymbolAddress((void**)&res1, g_res1);
    cudaGetSymbolAddress((void**)&norm, g_norm);

    // gate MLP
    concat_kernel<<<(BB * 2 * DD / 4) / 256, 256>>>(f1, f2, big);
    sgemm(big, gW1, gb1, h1, BB, HH, 2 * DD, ACT_NONE);
    ln_gelu_kernel<<<BB, HH / 4>>>(h1, gl1g, gl1b, HH);
    sgemm(h1, gW2, gb2, h2, BB, HH / 2, HH, ACT_NONE);
    ln_gelu_kernel<<<BB, HH / 8>>>(h2, gl2g, gl2b, HH / 2);
    sgemm(h2, gW3, gb3, gf, BB, DD, HH / 2, ACT_SIGMOID);
    gate_combine_kernel<<<(BB * DD / 4) / 256, 256>>>(gf, f1, f2);

    // attention
    sgemm(gf, qW, qb, q,  BB, DD, DD, ACT_NONE);
    sgemm(f1, kW, kb, k1, BB, DD, DD, ACT_NONE);
    sgemm(f2, kW, kb, k2, BB, DD, DD, ACT_NONE);
    sgemm(f1, vW, vb, v1, BB, DD, DD, ACT_NONE);
    sgemm(f2, vW, vb, v2, BB, DD, DD, ACT_NONE);
    attn_score_kernel<<<BB, 256>>>(q, k1, k2, w1v);
    attn_ln_kernel<<<BB, 256>>>(gf, v1, v2, w1v, alng, alnb, gated);

    // residual + LN1
    add_ln_kernel<<<BB, 256>>>(gated, f1, ln1g, ln1b, res1);

    // aspect BN
    bn_count_kernel<<<1, 256>>>(ids);
    bn_partial_kernel<<<dim3(DD / 256, NG), 256>>>(res1, ids);
    bn_finalize_kernel<<<(AA * DD + 255) / 256, 256>>>();
    bn_apply_kernel<<<(BB * DD / 4) / 256, 256>>>(res1, ids, bng, bnb, norm);

    // FFN (mid reuses g_big, output reuses g_q)
    sgemm(norm, fW1, fb1, big, BB, 2 * DD, DD, ACT_GELU);
    sgemm(big, fW2, fb2, q, BB, DD, 2 * DD, ACT_NONE);
    add_ln_kernel<<<BB, 256>>>(q, norm, ln2g, ln2b, (float*)d_out);
}

// round 2
// speedup vs baseline: 1.4125x; 1.4125x over previous
#include <cuda_runtime.h>
#include <mma.h>
#include <math.h>

using namespace nvcuda;

// ---------------- problem constants ----------------
#define BB 8192
#define DD 2048
#define HH 512
#define AA 3
#define EPS 1e-5f

#define ROWG 128
#define NG (BB / ROWG)   // 64

// ---------------- scratch (static device globals; no allocation) ------------
__device__ float g_big[BB * 2 * DD];      // hcat, later FFN mid
__device__ float g_h1[BB * HH];
__device__ float g_h2[BB * (HH / 2)];
__device__ float g_gf[BB * DD];           // gate -> gated features (in place)
__device__ float g_q[BB * DD];            // later reused for FFN output
__device__ float g_k1[BB * DD];
__device__ float g_k2[BB * DD];
__device__ float g_v1[BB * DD];
__device__ float g_v2[BB * DD];
__device__ float g_w1v[BB];
__device__ float g_gated[BB * DD];
__device__ float g_res1[BB * DD];
__device__ float g_norm[BB * DD];
__device__ float g_psum[NG * AA * DD];
__device__ float g_psq[NG * AA * DD];
__device__ float g_mean[AA * DD];
__device__ float g_istd[AA * DD];
__device__ int   g_cnt[AA];

// ---------------- helpers ----------------
__device__ __forceinline__ float gelu_f(float x) {
    return 0.5f * x * (1.0f + erff(x * 0.70710678118654752440f));
}

__device__ __forceinline__ void blockReduce2(float& a, float& b) {
    __shared__ float sa[32], sb[32];
    int lane = threadIdx.x & 31, wid = threadIdx.x >> 5;
    #pragma unroll
    for (int o = 16; o > 0; o >>= 1) {
        a += __shfl_xor_sync(0xffffffffu, a, o);
        b += __shfl_xor_sync(0xffffffffu, b, o);
    }
    if (lane == 0) { sa[wid] = a; sb[wid] = b; }
    __syncthreads();
    int nw = blockDim.x >> 5;
    if (wid == 0) {
        a = (lane < nw) ? sa[lane] : 0.f;
        b = (lane < nw) ? sb[lane] : 0.f;
        #pragma unroll
        for (int o = 16; o > 0; o >>= 1) {
            a += __shfl_xor_sync(0xffffffffu, a, o);
            b += __shfl_xor_sync(0xffffffffu, b, o);
        }
        if (lane == 0) { sa[0] = a; sb[0] = b; }
    }
    __syncthreads();
    a = sa[0]; b = sb[0];
}

// ---------------- TF32 tensor-core GEMM ----------------
// C[M,N] = act(A[M,K] @ W[K,N] + bias)
#define BM 128
#define BN 128
#define BK 32
#define APITCH 36        // 128x36 padded A tile (floats)
#define BPITCH 132       // 32x132 padded B tile (floats)
#define SPITCH 68        // epilogue staging pitch
#define ASZ (BM * APITCH)        // 4608
#define BSZ (BK * BPITCH)        // 4224
#define SMEM_FLOATS (2 * ASZ + 2 * BSZ)   // 17664 floats = 70656 B
#define ACT_NONE 0
#define ACT_GELU 1
#define ACT_SIGMOID 2

__device__ __forceinline__ void cp_async16(void* smem_ptr, const void* gmem_ptr) {
    unsigned saddr = (unsigned)__cvta_generic_to_shared(smem_ptr);
    asm volatile("cp.async.cg.shared.global [%0], [%1], 16;\n" :: "r"(saddr), "l"(gmem_ptr));
}
__device__ __forceinline__ void cp_commit() { asm volatile("cp.async.commit_group;\n"); }
__device__ __forceinline__ void cp_wait1() { asm volatile("cp.async.wait_group 1;\n"); }
__device__ __forceinline__ void cp_wait0() { asm volatile("cp.async.wait_group 0;\n"); }

__global__ __launch_bounds__(256)
void tf32gemm_kernel(const float* __restrict__ A, const float* __restrict__ W,
                     const float* __restrict__ bias, float* __restrict__ C,
                     int M, int N, int K, int act) {
    extern __shared__ float sm[];
    float* As = sm;                 // 2 buffers of ASZ
    float* Bs = sm + 2 * ASZ;       // 2 buffers of BSZ

    int tid = threadIdx.x;
    int bx = blockIdx.x;   // N tile
    int by = blockIdx.y;   // M tile
    int warp = tid >> 5;
    int lane = tid & 31;
    int wm = warp & 3;     // 4 warps along M (32 rows each)
    int wn = warp >> 2;    // 2 warps along N (64 cols each)

    const float* Ab = A + (size_t)by * BM * K;
    const float* Wb = W + (size_t)bx * BN;

    // A loader mapping: 1024 chunks of 16B; chunk = tid + p*256
    int a_row = tid >> 3;          // 0..31 per pass
    int a_c4 = (tid & 7) * 4;      // 0..28
    int b_row = tid >> 5;          // 0..7 per pass
    int b_c4 = (tid & 31) * 4;     // 0..124

    wmma::fragment<wmma::accumulator, 16, 16, 8, float> acc[2][4];
    #pragma unroll
    for (int i = 0; i < 2; i++)
        #pragma unroll
        for (int j = 0; j < 4; j++) wmma::fill_fragment(acc[i][j], 0.f);

    int ksteps = K / BK;

    // ---- prologue: load stage 0 ----
    {
        float* Ad = As;
        float* Bd = Bs;
        #pragma unroll
        for (int p = 0; p < 4; p++) {
            int r = a_row + p * 32;
            cp_async16(&Ad[r * APITCH + a_c4], Ab + (size_t)r * K + a_c4);
        }
        #pragma unroll
        for (int p = 0; p < 4; p++) {
            int r = b_row + p * 8;
            cp_async16(&Bd[r * BPITCH + b_c4], Wb + (size_t)r * N + b_c4);
        }
        cp_commit();
    }

    for (int s = 0; s < ksteps; s++) {
        if (s + 1 < ksteps) {
            int buf = (s + 1) & 1;
            int k0 = (s + 1) * BK;
            float* Ad = As + buf * ASZ;
            float* Bd = Bs + buf * BSZ;
            #pragma unroll
            for (int p = 0; p < 4; p++) {
                int r = a_row + p * 32;
                cp_async16(&Ad[r * APITCH + a_c4], Ab + (size_t)r * K + k0 + a_c4);
            }
            #pragma unroll
            for (int p = 0; p < 4; p++) {
                int r = b_row + p * 8;
                cp_async16(&Bd[r * BPITCH + b_c4], Wb + (size_t)(k0 + r) * N + b_c4);
            }
            cp_commit();
            cp_wait1();
        } else {
            cp_wait0();
        }
        __syncthreads();

        int buf = s & 1;
        const float* Ac = As + buf * ASZ;
        const float* Bc = Bs + buf * BSZ;
        #pragma unroll
        for (int kk = 0; kk < BK / 8; kk++) {
            wmma::fragment<wmma::matrix_a, 16, 16, 8, wmma::precision::tf32, wmma::row_major> af[2];
            wmma::fragment<wmma::matrix_b, 16, 16, 8, wmma::precision::tf32, wmma::row_major> bf[4];
            #pragma unroll
            for (int i = 0; i < 2; i++) {
                wmma::load_matrix_sync(af[i], Ac + (wm * 32 + i * 16) * APITCH + kk * 8, APITCH);
                #pragma unroll
                for (int t = 0; t < af[i].num_elements; t++)
                    af[i].x[t] = wmma::__float_to_tf32(af[i].x[t]);
            }
            #pragma unroll
            for (int j = 0; j < 4; j++) {
                wmma::load_matrix_sync(bf[j], Bc + (kk * 8) * BPITCH + wn * 64 + j * 16, BPITCH);
                #pragma unroll
                for (int t = 0; t < bf[j].num_elements; t++)
                    bf[j].x[t] = wmma::__float_to_tf32(bf[j].x[t]);
            }
            #pragma unroll
            for (int i = 0; i < 2; i++)
                #pragma unroll
                for (int j = 0; j < 4; j++)
                    wmma::mma_sync(acc[i][j], af[i], bf[j], acc[i][j]);
        }
        __syncthreads();
    }

    // ---- epilogue: stage through smem, fuse bias + act ----
    float* stg = sm + warp * (32 * SPITCH);
    #pragma unroll
    for (int i = 0; i < 2; i++)
        #pragma unroll
        for (int j = 0; j < 4; j++)
            wmma::store_matrix_sync(stg + (i * 16) * SPITCH + j * 16, acc[i][j], SPITCH,
                                    wmma::mem_row_major);
    __syncwarp();

    int grow = by * BM + wm * 32 + lane;
    int gcol0 = bx * BN + wn * 64;
    const float* brow = bias + gcol0;
    float* crow = C + (size_t)grow * N + gcol0;
    const float* srow = stg + lane * SPITCH;
    #pragma unroll
    for (int c4 = 0; c4 < 16; c4++) {
        float4 v = *(const float4*)(srow + c4 * 4);
        float4 bv = *(const float4*)(brow + c4 * 4);
        v.x += bv.x; v.y += bv.y; v.z += bv.z; v.w += bv.w;
        if (act == ACT_GELU) {
            v.x = gelu_f(v.x); v.y = gelu_f(v.y); v.z = gelu_f(v.z); v.w = gelu_f(v.w);
        } else if (act == ACT_SIGMOID) {
            v.x = 1.f / (1.f + expf(-v.x)); v.y = 1.f / (1.f + expf(-v.y));
            v.z = 1.f / (1.f + expf(-v.z)); v.w = 1.f / (1.f + expf(-v.w));
        }
        *(float4*)(crow + c4 * 4) = v;
    }
}

// ---------------- elementwise / rowwise kernels ----------------
__global__ void concat_kernel(const float* __restrict__ f1, const float* __restrict__ f2,
                              float* __restrict__ out) {
    int i4 = blockIdx.x * blockDim.x + threadIdx.x;
    int row = i4 >> 10;
    int c4 = i4 & 1023;
    float4 v;
    if (c4 < 512) v = ((const float4*)f1)[(size_t)row * 512 + c4];
    else          v = ((const float4*)f2)[(size_t)row * 512 + (c4 - 512)];
    ((float4*)out)[i4] = v;
}

__global__ void ln_gelu_kernel(float* __restrict__ x, const float* __restrict__ g,
                               const float* __restrict__ b, int N) {
    int row = blockIdx.x, t = threadIdx.x;
    float4* X = (float4*)(x + (size_t)row * N);
    float4 v = X[t];
    float s = v.x + v.y + v.z + v.w;
    float q = v.x * v.x + v.y * v.y + v.z * v.z + v.w * v.w;
    blockReduce2(s, q);
    float mu = s / N;
    float is = rsqrtf(q / N - mu * mu + EPS);
    float4 gv = ((const float4*)g)[t];
    float4 bv = ((const float4*)b)[t];
    v.x = gelu_f((v.x - mu) * is * gv.x + bv.x);
    v.y = gelu_f((v.y - mu) * is * gv.y + bv.y);
    v.z = gelu_f((v.z - mu) * is * gv.z + bv.z);
    v.w = gelu_f((v.w - mu) * is * gv.w + bv.w);
    X[t] = v;
}

__global__ void gate_combine_kernel(float* __restrict__ gate_gf,
                                    const float* __restrict__ f1,
                                    const float* __restrict__ f2) {
    int i = blockIdx.x * blockDim.x + threadIdx.x;
    float4 g = ((float4*)gate_gf)[i];
    float4 a = ((const float4*)f1)[i];
    float4 b = ((const float4*)f2)[i];
    float4 r;
    r.x = g.x * a.x + (1.f - g.x) * b.x;
    r.y = g.y * a.y + (1.f - g.y) * b.y;
    r.z = g.z * a.z + (1.f - g.z) * b.z;
    r.w = g.w * a.w + (1.f - g.w) * b.w;
    ((float4*)gate_gf)[i] = r;
}

__global__ void attn_score_kernel(const float* __restrict__ q, const float* __restrict__ k1,
                                  const float* __restrict__ k2, float* __restrict__ w1v) {
    int row = blockIdx.x, t = threadIdx.x;
    const float4* Q = (const float4*)(q + (size_t)row * DD);
    const float4* K1 = (const float4*)(k1 + (size_t)row * DD);
    const float4* K2 = (const float4*)(k2 + (size_t)row * DD);
    float s1 = 0.f, s2 = 0.f;
    #pragma unroll
    for (int j = 0; j < 2; j++) {
        int c = t + j * 256;
        float4 a = Q[c], b = K1[c], d = K2[c];
        s1 += a.x * b.x + a.y * b.y + a.z * b.z + a.w * b.w;
        s2 += a.x * d.x + a.y * d.y + a.z * d.z + a.w * d.w;
    }
    blockReduce2(s1, s2);
    if (t == 0) {
        float inv = 1.f / sqrtf((float)DD);
        s1 *= inv; s2 *= inv;
        float m = fmaxf(s1, s2);
        float e1 = expf(s1 - m), e2 = expf(s2 - m);
        w1v[row] = e1 / (e1 + e2);
    }
}

__global__ void attn_ln_kernel(const float* __restrict__ gf, const float* __restrict__ v1,
                               const float* __restrict__ v2, const float* __restrict__ w1v,
                               const float* __restrict__ g, const float* __restrict__ b,
                               float* __restrict__ out) {
    int row = blockIdx.x, t = threadIdx.x;
    const float4* GF = (const float4*)(gf + (size_t)row * DD);
    const float4* V1 = (const float4*)(v1 + (size_t)row * DD);
    const float4* V2 = (const float4*)(v2 + (size_t)row * DD);
    float w1 = w1v[row], w2 = 1.f - w1;
    float4 a[2];
    float s = 0.f, q = 0.f;
    #pragma unroll
    for (int j = 0; j < 2; j++) {
        int c = t + j * 256;
        float4 x = GF[c], y = V1[c], z = V2[c];
        float4 r;
        r.x = x.x + w1 * y.x + w2 * z.x;
        r.y = x.y + w1 * y.y + w2 * z.y;
        r.z = x.z + w1 * y.z + w2 * z.z;
        r.w = x.w + w1 * y.w + w2 * z.w;
        a[j] = r;
        s += r.x + r.y + r.z + r.w;
        q += r.x * r.x + r.y * r.y + r.z * r.z + r.w * r.w;
    }
    blockReduce2(s, q);
    float mu = s / DD;
    float is = rsqrtf(q / DD - mu * mu + EPS);
    #pragma unroll
    for (int j = 0; j < 2; j++) {
        int c = t + j * 256;
        float4 gv = ((const float4*)g)[c];
        float4 bv = ((const float4*)b)[c];
        float4 r = a[j];
        r.x = (r.x - mu) * is * gv.x + bv.x;
        r.y = (r.y - mu) * is * gv.y + bv.y;
        r.z = (r.z - mu) * is * gv.z + bv.z;
        r.w = (r.w - mu) * is * gv.w + bv.w;
        ((float4*)(out + (size_t)row * DD))[c] = r;
    }
}

__global__ void add_ln_kernel(const float* __restrict__ xa, const float* __restrict__ xb,
                              const float* __restrict__ g, const float* __restrict__ b,
                              float* __restrict__ out) {
    int row = blockIdx.x, t = threadIdx.x;
    const float4* XA = (const float4*)(xa + (size_t)row * DD);
    const float4* XB = (const float4*)(xb + (size_t)row * DD);
    float4 a[2];
    float s = 0.f, q = 0.f;
    #pragma unroll
    for (int j = 0; j < 2; j++) {
        int c = t + j * 256;
        float4 x = XA[c], y = XB[c];
        float4 r;
        r.x = x.x + y.x; r.y = x.y + y.y; r.z = x.z + y.z; r.w = x.w + y.w;
        a[j] = r;
        s += r.x + r.y + r.z + r.w;
        q += r.x * r.x + r.y * r.y + r.z * r.z + r.w * r.w;
    }
    blockReduce2(s, q);
    float mu = s / DD;
    float is = rsqrtf(q / DD - mu * mu + EPS);
    #pragma unroll
    for (int j = 0; j < 2; j++) {
        int c = t + j * 256;
        float4 gv = ((const float4*)g)[c];
        float4 bv = ((const float4*)b)[c];
        float4 r = a[j];
        r.x = (r.x - mu) * is * gv.x + bv.x;
        r.y = (r.y - mu) * is * gv.y + bv.y;
        r.z = (r.z - mu) * is * gv.z + bv.z;
        r.w = (r.w - mu) * is * gv.w + bv.w;
        ((float4*)(out + (size_t)row * DD))[c] = r;
    }
}

// ---------------- aspect BN (deterministic two-stage) ----------------
__global__ void bn_count_kernel(const int* __restrict__ ids) {
    __shared__ int c[AA];
    if (threadIdx.x < AA) c[threadIdx.x] = 0;
    __syncthreads();
    for (int i = threadIdx.x; i < BB; i += blockDim.x) atomicAdd(&c[ids[i]], 1);
    __syncthreads();
    if (threadIdx.x < AA) g_cnt[threadIdx.x] = c[threadIdx.x];
}

__global__ void bn_partial_kernel(const float* __restrict__ x, const int* __restrict__ ids) {
    int d = blockIdx.x * blockDim.x + threadIdx.x;
    int g0 = blockIdx.y * ROWG;
    __shared__ int sid[ROWG];
    for (int i = threadIdx.x; i < ROWG; i += blockDim.x) sid[i] = ids[g0 + i];
    __syncthreads();
    float s0 = 0.f, s1 = 0.f, s2 = 0.f, q0 = 0.f, q1 = 0.f, q2 = 0.f;
    for (int r = 0; r < ROWG; r++) {
        float v = x[(size_t)(g0 + r) * DD + d];
        int a = sid[r];
        float vv = v * v;
        if (a == 0)      { s0 += v; q0 += vv; }
        else if (a == 1) { s1 += v; q1 += vv; }
        else             { s2 += v; q2 += vv; }
    }
    size_t base = (size_t)blockIdx.y * AA * DD + d;
    g_psum[base]          = s0; g_psq[base]          = q0;
    g_psum[base + DD]     = s1; g_psq[base + DD]     = q1;
    g_psum[base + 2 * DD] = s2; g_psq[base + 2 * DD] = q2;
}

__global__ void bn_finalize_kernel() {
    int i = blockIdx.x * blockDim.x + threadIdx.x;
    if (i >= AA * DD) return;
    float s = 0.f, q = 0.f;
    for (int g = 0; g < NG; g++) {
        s += g_psum[(size_t)g * AA * DD + i];
        q += g_psq[(size_t)g * AA * DD + i];
    }
    int a = i / DD;
    float safe = fmaxf((float)g_cnt[a], 1.f);
    float m = s / safe;
    float var = q / safe - m * m;
    g_mean[i] = m;
    g_istd[i] = rsqrtf(var + EPS);
}

__global__ void bn_apply_kernel(const float* __restrict__ x, const int* __restrict__ ids,
                                const float* __restrict__ bng, const float* __restrict__ bnb,
                                float* __restrict__ out) {
    int i4 = blockIdx.x * blockDim.x + threadIdx.x;
    int row = i4 / (DD / 4);
    int c4 = i4 % (DD / 4);
    int a = ids[row];
    float4 v = ((const float4*)x)[i4];
    if (g_cnt[a] > 1) {
        size_t off = (size_t)a * DD / 4 + c4;
        float4 m = ((const float4*)g_mean)[off];
        float4 is = ((const float4*)g_istd)[off];
        float4 gv = ((const float4*)bng)[off];
        float4 bv = ((const float4*)bnb)[off];
        v.x = (v.x - m.x) * is.x * gv.x + bv.x;
        v.y = (v.y - m.y) * is.y * gv.y + bv.y;
        v.z = (v.z - m.z) * is.z * gv.z + bv.z;
        v.w = (v.w - m.w) * is.w * gv.w + bv.w;
    }
    ((float4*)out)[i4] = v;
}

// ---------------- launch ----------------
#define GEMM_SMEM_BYTES (SMEM_FLOATS * 4)

static inline void tgemm(const float* A, const float* W, const float* bias, float* C,
                         int M, int N, int K, int act) {
    dim3 grid(N / BN, M / BM);
    tf32gemm_kernel<<<grid, 256, GEMM_SMEM_BYTES>>>(A, W, bias, C, M, N, K, act);
}

extern "C" void kernel_launch(void* const* d_in, const int* in_sizes, int n_in,
                              void* d_out, int out_size) {
    const float* f1   = (const float*)d_in[0];
    const float* f2   = (const float*)d_in[1];
    const int*   ids  = (const int*)d_in[2];
    const float* gW1  = (const float*)d_in[3];
    const float* gb1  = (const float*)d_in[4];
    const float* gl1g = (const float*)d_in[5];
    const float* gl1b = (const float*)d_in[6];
    const float* gW2  = (const float*)d_in[7];
    const float* gb2  = (const float*)d_in[8];
    const float* gl2g = (const float*)d_in[9];
    const float* gl2b = (const float*)d_in[10];
    const float* gW3  = (const float*)d_in[11];
    const float* gb3  = (const float*)d_in[12];
    const float* qW   = (const float*)d_in[13];
    const float* qb   = (const float*)d_in[14];
    const float* kW   = (const float*)d_in[15];
    const float* kb   = (const float*)d_in[16];
    const float* vW   = (const float*)d_in[17];
    const float* vb   = (const float*)d_in[18];
    const float* alng = (const float*)d_in[19];
    const float* alnb = (const float*)d_in[20];
    const float* bng  = (const float*)d_in[21];
    const float* bnb  = (const float*)d_in[22];
    const float* ln1g = (const float*)d_in[23];
    const float* ln1b = (const float*)d_in[24];
    const float* fW1  = (const float*)d_in[25];
    const float* fb1  = (const float*)d_in[26];
    const float* fW2  = (const float*)d_in[27];
    const float* fb2  = (const float*)d_in[28];
    const float* ln2g = (const float*)d_in[29];
    const float* ln2b = (const float*)d_in[30];

    cudaFuncSetAttribute(tf32gemm_kernel, cudaFuncAttributeMaxDynamicSharedMemorySize,
                         GEMM_SMEM_BYTES);

    float *big, *h1, *h2, *gf, *q, *k1, *k2, *v1, *v2, *w1v, *gated, *res1, *norm;
    cudaGetSymbolAddress((void**)&big,  g_big);
    cudaGetSymbolAddress((void**)&h1,   g_h1);
    cudaGetSymbolAddress((void**)&h2,   g_h2);
    cudaGetSymbolAddress((void**)&gf,   g_gf);
    cudaGetSymbolAddress((void**)&q,    g_q);
    cudaGetSymbolAddress((void**)&k1,   g_k1);
    cudaGetSymbolAddress((void**)&k2,   g_k2);
    cudaGetSymbolAddress((void**)&v1,   g_v1);
    cudaGetSymbolAddress((void**)&v2,   g_v2);
    cudaGetSymbolAddress((void**)&w1v,  g_w1v);
    cudaGetSymbolAddress((void**)&gated, g_gated);
    cudaGetSymbolAddress((void**)&res1, g_res1);
    cudaGetSymbolAddress((void**)&norm, g_norm);

    // gate MLP
    concat_kernel<<<(BB * 2 * DD / 4) / 256, 256>>>(f1, f2, big);
    tgemm(big, gW1, gb1, h1, BB, HH, 2 * DD, ACT_NONE);
    ln_gelu_kernel<<<BB, HH / 4>>>(h1, gl1g, gl1b, HH);
    tgemm(h1, gW2, gb2, h2, BB, HH / 2, HH, ACT_NONE);
    ln_gelu_kernel<<<BB, HH / 8>>>(h2, gl2g, gl2b, HH / 2);
    tgemm(h2, gW3, gb3, gf, BB, DD, HH / 2, ACT_SIGMOID);
    gate_combine_kernel<<<(BB * DD / 4) / 256, 256>>>(gf, f1, f2);

    // attention
    tgemm(gf, qW, qb, q,  BB, DD, DD, ACT_NONE);
    tgemm(f1, kW, kb, k1, BB, DD, DD, ACT_NONE);
    tgemm(f2, kW, kb, k2, BB, DD, DD, ACT_NONE);
    tgemm(f1, vW, vb, v1, BB, DD, DD, ACT_NONE);
    tgemm(f2, vW, vb, v2, BB, DD, DD, ACT_NONE);
    attn_score_kernel<<<BB, 256>>>(q, k1, k2, w1v);
    attn_ln_kernel<<<BB, 256>>>(gf, v1, v2, w1v, alng, alnb, gated);

    // residual + LN1
    add_ln_kernel<<<BB, 256>>>(gated, f1, ln1g, ln1b, res1);

    // aspect BN
    bn_count_kernel<<<1, 256>>>(ids);
    bn_partial_kernel<<<dim3(DD / 256, NG), 256>>>(res1, ids);
    bn_finalize_kernel<<<(AA * DD + 255) / 256, 256>>>();
    bn_apply_kernel<<<(BB * DD / 4) / 256, 256>>>(res1, ids, bng, bnb, norm);

    // FFN (mid reuses g_big, output reuses g_q)
    tgemm(norm, fW1, fb1, big, BB, 2 * DD, DD, ACT_GELU);
    tgemm(big, fW2, fb2, q, BB, DD, 2 * DD, ACT_NONE);
    add_ln_kernel<<<BB, 256>>>(q, norm, ln2g, ln2b, (float*)d_out);
}

// round 3
// speedup vs baseline: 1.6491x; 1.1674x over previous
#include <cuda_runtime.h>
#include <mma.h>
#include <math.h>

using namespace nvcuda;

// ---------------- problem constants ----------------
#define BB 8192
#define DD 2048
#define HH 512
#define AA 3
#define EPS 1e-5f

#define ROWG 128
#define NG (BB / ROWG)   // 64

// ---------------- scratch (static device globals; no allocation) ------------
__device__ float g_big[BB * 2 * DD];      // hcat, later FFN mid
__device__ float g_h1[BB * HH];
__device__ float g_h2[BB * (HH / 2)];
__device__ float g_gf[BB * DD];           // gate -> gated features (in place)
__device__ float g_q[BB * DD];            // later reused for FFN output
__device__ float g_k1[BB * DD];
__device__ float g_k2[BB * DD];
__device__ float g_v1[BB * DD];
__device__ float g_v2[BB * DD];
__device__ float g_w1v[BB];
__device__ float g_gated[BB * DD];
__device__ float g_res1[BB * DD];
__device__ float g_norm[BB * DD];
__device__ float g_psum[NG * AA * DD];
__device__ float g_psq[NG * AA * DD];
__device__ float g_mean[AA * DD];
__device__ float g_istd[AA * DD];
__device__ int   g_cnt[AA];

// ---------------- helpers ----------------
__device__ __forceinline__ float gelu_f(float x) {
    return 0.5f * x * (1.0f + erff(x * 0.70710678118654752440f));
}

__device__ __forceinline__ void blockReduce2(float& a, float& b) {
    __shared__ float sa[32], sb[32];
    int lane = threadIdx.x & 31, wid = threadIdx.x >> 5;
    #pragma unroll
    for (int o = 16; o > 0; o >>= 1) {
        a += __shfl_xor_sync(0xffffffffu, a, o);
        b += __shfl_xor_sync(0xffffffffu, b, o);
    }
    if (lane == 0) { sa[wid] = a; sb[wid] = b; }
    __syncthreads();
    int nw = blockDim.x >> 5;
    if (wid == 0) {
        a = (lane < nw) ? sa[lane] : 0.f;
        b = (lane < nw) ? sb[lane] : 0.f;
        #pragma unroll
        for (int o = 16; o > 0; o >>= 1) {
            a += __shfl_xor_sync(0xffffffffu, a, o);
            b += __shfl_xor_sync(0xffffffffu, b, o);
        }
        if (lane == 0) { sa[0] = a; sb[0] = b; }
    }
    __syncthreads();
    a = sa[0]; b = sb[0];
}

// ---------------- TF32 tensor-core GEMM ----------------
// C[M,N] = act(A[M,K] @ W[K,N] + bias)
#define BM 128
#define BN 128
#define BK 32
#define NSTAGE 3
#define APITCH 36        // 128x36 padded A tile (floats)
#define BPITCH 132       // 32x132 padded B tile (floats)
#define SPITCH 68        // epilogue staging pitch
#define ASZ (BM * APITCH)        // 4608
#define BSZ (BK * BPITCH)        // 4224
#define SMEM_FLOATS (NSTAGE * (ASZ + BSZ))   // 26496 floats = 105984 B
#define ACT_NONE 0
#define ACT_GELU 1
#define ACT_SIGMOID 2

__device__ __forceinline__ void cp_async16(void* smem_ptr, const void* gmem_ptr) {
    unsigned saddr = (unsigned)__cvta_generic_to_shared(smem_ptr);
    asm volatile("cp.async.cg.shared.global [%0], [%1], 16;\n" :: "r"(saddr), "l"(gmem_ptr));
}
__device__ __forceinline__ void cp_commit() { asm volatile("cp.async.commit_group;\n"); }
__device__ __forceinline__ void cp_wait1() { asm volatile("cp.async.wait_group 1;\n"); }
__device__ __forceinline__ void cp_wait0() { asm volatile("cp.async.wait_group 0;\n"); }

__device__ __forceinline__ void load_stage(const float* __restrict__ Ab,
                                           const float* __restrict__ Wb,
                                           float* Ad, float* Bd, int k0,
                                           int K, int N,
                                           int a_row, int a_c4, int b_row, int b_c4) {
    #pragma unroll
    for (int p = 0; p < 4; p++) {
        int r = a_row + p * 32;
        cp_async16(&Ad[r * APITCH + a_c4], Ab + (size_t)r * K + k0 + a_c4);
    }
    #pragma unroll
    for (int p = 0; p < 4; p++) {
        int r = b_row + p * 8;
        cp_async16(&Bd[r * BPITCH + b_c4], Wb + (size_t)(k0 + r) * N + b_c4);
    }
    cp_commit();
}

__global__ __launch_bounds__(256, 2)
void tf32gemm_kernel(const float* __restrict__ A, const float* __restrict__ W,
                     const float* __restrict__ bias, float* __restrict__ C,
                     int M, int N, int K, int act) {
    extern __shared__ float sm[];
    float* As = sm;                      // NSTAGE buffers of ASZ
    float* Bs = sm + NSTAGE * ASZ;       // NSTAGE buffers of BSZ

    int tid = threadIdx.x;
    int bx = blockIdx.x;   // N tile
    int by = blockIdx.y;   // M tile
    int warp = tid >> 5;
    int lane = tid & 31;
    int wm = warp & 3;     // 4 warps along M (32 rows each)
    int wn = warp >> 2;    // 2 warps along N (64 cols each)

    const float* Ab = A + (size_t)by * BM * K;
    const float* Wb = W + (size_t)bx * BN;

    int a_row = tid >> 3;          // 0..31 per pass
    int a_c4 = (tid & 7) * 4;      // 0..28
    int b_row = tid >> 5;          // 0..7 per pass
    int b_c4 = (tid & 31) * 4;     // 0..124

    wmma::fragment<wmma::accumulator, 16, 16, 8, float> acc[2][4];
    #pragma unroll
    for (int i = 0; i < 2; i++)
        #pragma unroll
        for (int j = 0; j < 4; j++) wmma::fill_fragment(acc[i][j], 0.f);

    int ksteps = K / BK;   // >= 8 for all shapes here

    // ---- prologue: stages 0 and 1 ----
    load_stage(Ab, Wb, As, Bs, 0, K, N, a_row, a_c4, b_row, b_c4);
    load_stage(Ab, Wb, As + ASZ, Bs + BSZ, BK, K, N, a_row, a_c4, b_row, b_c4);

    for (int s = 0; s < ksteps; s++) {
        if (s + 1 < ksteps) cp_wait1(); else cp_wait0();
        __syncthreads();

        int buf = s % NSTAGE;
        const float* Ac = As + buf * ASZ;
        const float* Bc = Bs + buf * BSZ;
        #pragma unroll
        for (int kk = 0; kk < BK / 8; kk++) {
            wmma::fragment<wmma::matrix_a, 16, 16, 8, wmma::precision::tf32, wmma::row_major> af[2];
            wmma::fragment<wmma::matrix_b, 16, 16, 8, wmma::precision::tf32, wmma::row_major> bf[4];
            #pragma unroll
            for (int i = 0; i < 2; i++) {
                wmma::load_matrix_sync(af[i], Ac + (wm * 32 + i * 16) * APITCH + kk * 8, APITCH);
                #pragma unroll
                for (int t = 0; t < af[i].num_elements; t++)
                    af[i].x[t] = wmma::__float_to_tf32(af[i].x[t]);
            }
            #pragma unroll
            for (int j = 0; j < 4; j++) {
                // no cvt on B: hardware truncation to tf32 (keeps precision
                // within ~1 ulp_tf32, removes 16 ALU ops per kk-step)
                wmma::load_matrix_sync(bf[j], Bc + (kk * 8) * BPITCH + wn * 64 + j * 16, BPITCH);
            }
            #pragma unroll
            for (int i = 0; i < 2; i++)
                #pragma unroll
                for (int j = 0; j < 4; j++)
                    wmma::mma_sync(acc[i][j], af[i], bf[j], acc[i][j]);
        }
        __syncthreads();

        if (s + 2 < ksteps) {
            int nbuf = (s + 2) % NSTAGE;
            load_stage(Ab, Wb, As + nbuf * ASZ, Bs + nbuf * BSZ, (s + 2) * BK,
                       K, N, a_row, a_c4, b_row, b_c4);
        }
    }

    // ---- epilogue: stage through smem, fuse bias + act ----
    float* stg = sm + warp * (32 * SPITCH);
    #pragma unroll
    for (int i = 0; i < 2; i++)
        #pragma unroll
        for (int j = 0; j < 4; j++)
            wmma::store_matrix_sync(stg + (i * 16) * SPITCH + j * 16, acc[i][j], SPITCH,
                                    wmma::mem_row_major);
    __syncwarp();

    int grow = by * BM + wm * 32 + lane;
    int gcol0 = bx * BN + wn * 64;
    const float* brow = bias + gcol0;
    float* crow = C + (size_t)grow * N + gcol0;
    const float* srow = stg + lane * SPITCH;
    #pragma unroll
    for (int c4 = 0; c4 < 16; c4++) {
        float4 v = *(const float4*)(srow + c4 * 4);
        float4 bv = *(const float4*)(brow + c4 * 4);
        v.x += bv.x; v.y += bv.y; v.z += bv.z; v.w += bv.w;
        if (act == ACT_GELU) {
            v.x = gelu_f(v.x); v.y = gelu_f(v.y); v.z = gelu_f(v.z); v.w = gelu_f(v.w);
        } else if (act == ACT_SIGMOID) {
            v.x = 1.f / (1.f + expf(-v.x)); v.y = 1.f / (1.f + expf(-v.y));
            v.z = 1.f / (1.f + expf(-v.z)); v.w = 1.f / (1.f + expf(-v.w));
        }
        *(float4*)(crow + c4 * 4) = v;
    }
}

// ---------------- elementwise / rowwise kernels ----------------
__global__ void concat_kernel(const float* __restrict__ f1, const float* __restrict__ f2,
                              float* __restrict__ out) {
    int i4 = blockIdx.x * blockDim.x + threadIdx.x;
    int row = i4 >> 10;
    int c4 = i4 & 1023;
    float4 v;
    if (c4 < 512) v = ((const float4*)f1)[(size_t)row * 512 + c4];
    else          v = ((const float4*)f2)[(size_t)row * 512 + (c4 - 512)];
    ((float4*)out)[i4] = v;
}

__global__ void ln_gelu_kernel(float* __restrict__ x, const float* __restrict__ g,
                               const float* __restrict__ b, int N) {
    int row = blockIdx.x, t = threadIdx.x;
    float4* X = (float4*)(x + (size_t)row * N);
    float4 v = X[t];
    float s = v.x + v.y + v.z + v.w;
    float q = v.x * v.x + v.y * v.y + v.z * v.z + v.w * v.w;
    blockReduce2(s, q);
    float mu = s / N;
    float is = rsqrtf(q / N - mu * mu + EPS);
    float4 gv = ((const float4*)g)[t];
    float4 bv = ((const float4*)b)[t];
    v.x = gelu_f((v.x - mu) * is * gv.x + bv.x);
    v.y = gelu_f((v.y - mu) * is * gv.y + bv.y);
    v.z = gelu_f((v.z - mu) * is * gv.z + bv.z);
    v.w = gelu_f((v.w - mu) * is * gv.w + bv.w);
    X[t] = v;
}

__global__ void gate_combine_kernel(float* __restrict__ gate_gf,
                                    const float* __restrict__ f1,
                                    const float* __restrict__ f2) {
    int i = blockIdx.x * blockDim.x + threadIdx.x;
    float4 g = ((float4*)gate_gf)[i];
    float4 a = ((const float4*)f1)[i];
    float4 b = ((const float4*)f2)[i];
    float4 r;
    r.x = g.x * a.x + (1.f - g.x) * b.x;
    r.y = g.y * a.y + (1.f - g.y) * b.y;
    r.z = g.z * a.z + (1.f - g.z) * b.z;
    r.w = g.w * a.w + (1.f - g.w) * b.w;
    ((float4*)gate_gf)[i] = r;
}

__global__ void attn_score_kernel(const float* __restrict__ q, const float* __restrict__ k1,
                                  const float* __restrict__ k2, float* __restrict__ w1v) {
    int row = blockIdx.x, t = threadIdx.x;
    const float4* Q = (const float4*)(q + (size_t)row * DD);
    const float4* K1 = (const float4*)(k1 + (size_t)row * DD);
    const float4* K2 = (const float4*)(k2 + (size_t)row * DD);
    float s1 = 0.f, s2 = 0.f;
    #pragma unroll
    for (int j = 0; j < 2; j++) {
        int c = t + j * 256;
        float4 a = Q[c], b = K1[c], d = K2[c];
        s1 += a.x * b.x + a.y * b.y + a.z * b.z + a.w * b.w;
        s2 += a.x * d.x + a.y * d.y + a.z * d.z + a.w * d.w;
    }
    blockReduce2(s1, s2);
    if (t == 0) {
        float inv = 1.f / sqrtf((float)DD);
        s1 *= inv; s2 *= inv;
        float m = fmaxf(s1, s2);
        float e1 = expf(s1 - m), e2 = expf(s2 - m);
        w1v[row] = e1 / (e1 + e2);
    }
}

__global__ void attn_ln_kernel(const float* __restrict__ gf, const float* __restrict__ v1,
                               const float* __restrict__ v2, const float* __restrict__ w1v,
                               const float* __restrict__ g, const float* __restrict__ b,
                               float* __restrict__ out) {
    int row = blockIdx.x, t = threadIdx.x;
    const float4* GF = (const float4*)(gf + (size_t)row * DD);
    const float4* V1 = (const float4*)(v1 + (size_t)row * DD);
    const float4* V2 = (const float4*)(v2 + (size_t)row * DD);
    float w1 = w1v[row], w2 = 1.f - w1;
    float4 a[2];
    float s = 0.f, q = 0.f;
    #pragma unroll
    for (int j = 0; j < 2; j++) {
        int c = t + j * 256;
        float4 x = GF[c], y = V1[c], z = V2[c];
        float4 r;
        r.x = x.x + w1 * y.x + w2 * z.x;
        r.y = x.y + w1 * y.y + w2 * z.y;
        r.z = x.z + w1 * y.z + w2 * z.z;
        r.w = x.w + w1 * y.w + w2 * z.w;
        a[j] = r;
        s += r.x + r.y + r.z + r.w;
        q += r.x * r.x + r.y * r.y + r.z * r.z + r.w * r.w;
    }
    blockReduce2(s, q);
    float mu = s / DD;
    float is = rsqrtf(q / DD - mu * mu + EPS);
    #pragma unroll
    for (int j = 0; j < 2; j++) {
        int c = t + j * 256;
        float4 gv = ((const float4*)g)[c];
        float4 bv = ((const float4*)b)[c];
        float4 r = a[j];
        r.x = (r.x - mu) * is * gv.x + bv.x;
        r.y = (r.y - mu) * is * gv.y + bv.y;
        r.z = (r.z - mu) * is * gv.z + bv.z;
        r.w = (r.w - mu) * is * gv.w + bv.w;
        ((float4*)(out + (size_t)row * DD))[c] = r;
    }
}

__global__ void add_ln_kernel(const float* __restrict__ xa, const float* __restrict__ xb,
                              const float* __restrict__ g, const float* __restrict__ b,
                              float* __restrict__ out) {
    int row = blockIdx.x, t = threadIdx.x;
    const float4* XA = (const float4*)(xa + (size_t)row * DD);
    const float4* XB = (const float4*)(xb + (size_t)row * DD);
    float4 a[2];
    float s = 0.f, q = 0.f;
    #pragma unroll
    for (int j = 0; j < 2; j++) {
        int c = t + j * 256;
        float4 x = XA[c], y = XB[c];
        float4 r;
        r.x = x.x + y.x; r.y = x.y + y.y; r.z = x.z + y.z; r.w = x.w + y.w;
        a[j] = r;
        s += r.x + r.y + r.z + r.w;
        q += r.x * r.x + r.y * r.y + r.z * r.z + r.w * r.w;
    }
    blockReduce2(s, q);
    float mu = s / DD;
    float is = rsqrtf(q / DD - mu * mu + EPS);
    #pragma unroll
    for (int j = 0; j < 2; j++) {
        int c = t + j * 256;
        float4 gv = ((const float4*)g)[c];
        float4 bv = ((const float4*)b)[c];
        float4 r = a[j];
        r.x = (r.x - mu) * is * gv.x + bv.x;
        r.y = (r.y - mu) * is * gv.y + bv.y;
        r.z = (r.z - mu) * is * gv.z + bv.z;
        r.w = (r.w - mu) * is * gv.w + bv.w;
        ((float4*)(out + (size_t)row * DD))[c] = r;
    }
}

// ---------------- aspect BN (deterministic two-stage) ----------------
__global__ void bn_count_kernel(const int* __restrict__ ids) {
    __shared__ int c[AA];
    if (threadIdx.x < AA) c[threadIdx.x] = 0;
    __syncthreads();
    for (int i = threadIdx.x; i < BB; i += blockDim.x) atomicAdd(&c[ids[i]], 1);
    __syncthreads();
    if (threadIdx.x < AA) g_cnt[threadIdx.x] = c[threadIdx.x];
}

__global__ void bn_partial_kernel(const float* __restrict__ x, const int* __restrict__ ids) {
    int d = blockIdx.x * blockDim.x + threadIdx.x;
    int g0 = blockIdx.y * ROWG;
    __shared__ int sid[ROWG];
    for (int i = threadIdx.x; i < ROWG; i += blockDim.x) sid[i] = ids[g0 + i];
    __syncthreads();
    float s0 = 0.f, s1 = 0.f, s2 = 0.f, q0 = 0.f, q1 = 0.f, q2 = 0.f;
    for (int r = 0; r < ROWG; r++) {
        float v = x[(size_t)(g0 + r) * DD + d];
        int a = sid[r];
        float vv = v * v;
        if (a == 0)      { s0 += v; q0 += vv; }
        else if (a == 1) { s1 += v; q1 += vv; }
        else             { s2 += v; q2 += vv; }
    }
    size_t base = (size_t)blockIdx.y * AA * DD + d;
    g_psum[base]          = s0; g_psq[base]          = q0;
    g_psum[base + DD]     = s1; g_psq[base + DD]     = q1;
    g_psum[base + 2 * DD] = s2; g_psq[base + 2 * DD] = q2;
}

__global__ void bn_finalize_kernel() {
    int i = blockIdx.x * blockDim.x + threadIdx.x;
    if (i >= AA * DD) return;
    float s = 0.f, q = 0.f;
    for (int g = 0; g < NG; g++) {
        s += g_psum[(size_t)g * AA * DD + i];
        q += g_psq[(size_t)g * AA * DD + i];
    }
    int a = i / DD;
    float safe = fmaxf((float)g_cnt[a], 1.f);
    float m = s / safe;
    float var = q / safe - m * m;
    g_mean[i] = m;
    g_istd[i] = rsqrtf(var + EPS);
}

__global__ void bn_apply_kernel(const float* __restrict__ x, const int* __restrict__ ids,
                                const float* __restrict__ bng, const float* __restrict__ bnb,
                                float* __restrict__ out) {
    int i4 = blockIdx.x * blockDim.x + threadIdx.x;
    int row = i4 / (DD / 4);
    int c4 = i4 % (DD / 4);
    int a = ids[row];
    float4 v = ((const float4*)x)[i4];
    if (g_cnt[a] > 1) {
        size_t off = (size_t)a * DD / 4 + c4;
        float4 m = ((const float4*)g_mean)[off];
        float4 is = ((const float4*)g_istd)[off];
        float4 gv = ((const float4*)bng)[off];
        float4 bv = ((const float4*)bnb)[off];
        v.x = (v.x - m.x) * is.x * gv.x + bv.x;
        v.y = (v.y - m.y) * is.y * gv.y + bv.y;
        v.z = (v.z - m.z) * is.z * gv.z + bv.z;
        v.w = (v.w - m.w) * is.w * gv.w + bv.w;
    }
    ((float4*)out)[i4] = v;
}

// ---------------- launch ----------------
#define GEMM_SMEM_BYTES (SMEM_FLOATS * 4)

static inline void tgemm(const float* A, const float* W, const float* bias, float* C,
                         int M, int N, int K, int act) {
    dim3 grid(N / BN, M / BM);
    tf32gemm_kernel<<<grid, 256, GEMM_SMEM_BYTES>>>(A, W, bias, C, M, N, K, act);
}

extern "C" void kernel_launch(void* const* d_in, const int* in_sizes, int n_in,
                              void* d_out, int out_size) {
    const float* f1   = (const float*)d_in[0];
    const float* f2   = (const float*)d_in[1];
    const int*   ids  = (const int*)d_in[2];
    const float* gW1  = (const float*)d_in[3];
    const float* gb1  = (const float*)d_in[4];
    const float* gl1g = (const float*)d_in[5];
    const float* gl1b = (const float*)d_in[6];
    const float* gW2  = (const float*)d_in[7];
    const float* gb2  = (const float*)d_in[8];
    const float* gl2g = (const float*)d_in[9];
    const float* gl2b = (const float*)d_in[10];
    const float* gW3  = (const float*)d_in[11];
    const float* gb3  = (const float*)d_in[12];
    const float* qW   = (const float*)d_in[13];
    const float* qb   = (const float*)d_in[14];
    const float* kW   = (const float*)d_in[15];
    const float* kb   = (const float*)d_in[16];
    const float* vW   = (const float*)d_in[17];
    const float* vb   = (const float*)d_in[18];
    const float* alng = (const float*)d_in[19];
    const float* alnb = (const float*)d_in[20];
    const float* bng  = (const float*)d_in[21];
    const float* bnb  = (const float*)d_in[22];
    const float* ln1g = (const float*)d_in[23];
    const float* ln1b = (const float*)d_in[24];
    const float* fW1  = (const float*)d_in[25];
    const float* fb1  = (const float*)d_in[26];
    const float* fW2  = (const float*)d_in[27];
    const float* fb2  = (const float*)d_in[28];
    const float* ln2g = (const float*)d_in[29];
    const float* ln2b = (const float*)d_in[30];

    cudaFuncSetAttribute(tf32gemm_kernel, cudaFuncAttributeMaxDynamicSharedMemorySize,
                         GEMM_SMEM_BYTES);

    float *big, *h1, *h2, *gf, *q, *k1, *k2, *v1, *v2, *w1v, *gated, *res1, *norm;
    cudaGetSymbolAddress((void**)&big,  g_big);
    cudaGetSymbolAddress((void**)&h1,   g_h1);
    cudaGetSymbolAddress((void**)&h2,   g_h2);
    cudaGetSymbolAddress((void**)&gf,   g_gf);
    cudaGetSymbolAddress((void**)&q,    g_q);
    cudaGetSymbolAddress((void**)&k1,   g_k1);
    cudaGetSymbolAddress((void**)&k2,   g_k2);
    cudaGetSymbolAddress((void**)&v1,   g_v1);
    cudaGetSymbolAddress((void**)&v2,   g_v2);
    cudaGetSymbolAddress((void**)&w1v,  g_w1v);
    cudaGetSymbolAddress((void**)&gated, g_gated);
    cudaGetSymbolAddress((void**)&res1, g_res1);
    cudaGetSymbolAddress((void**)&norm, g_norm);

    // gate MLP
    concat_kernel<<<(BB * 2 * DD / 4) / 256, 256>>>(f1, f2, big);
    tgemm(big, gW1, gb1, h1, BB, HH, 2 * DD, ACT_NONE);
    ln_gelu_kernel<<<BB, HH / 4>>>(h1, gl1g, gl1b, HH);
    tgemm(h1, gW2, gb2, h2, BB, HH / 2, HH, ACT_NONE);
    ln_gelu_kernel<<<BB, HH / 8>>>(h2, gl2g, gl2b, HH / 2);
    tgemm(h2, gW3, gb3, gf, BB, DD, HH / 2, ACT_SIGMOID);
    gate_combine_kernel<<<(BB * DD / 4) / 256, 256>>>(gf, f1, f2);

    // attention
    tgemm(gf, qW, qb, q,  BB, DD, DD, ACT_NONE);
    tgemm(f1, kW, kb, k1, BB, DD, DD, ACT_NONE);
    tgemm(f2, kW, kb, k2, BB, DD, DD, ACT_NONE);
    tgemm(f1, vW, vb, v1, BB, DD, DD, ACT_NONE);
    tgemm(f2, vW, vb, v2, BB, DD, DD, ACT_NONE);
    attn_score_kernel<<<BB, 256>>>(q, k1, k2, w1v);
    attn_ln_kernel<<<BB, 256>>>(gf, v1, v2, w1v, alng, alnb, gated);

    // residual + LN1
    add_ln_kernel<<<BB, 256>>>(gated, f1, ln1g, ln1b, res1);

    // aspect BN
    bn_count_kernel<<<1, 256>>>(ids);
    bn_partial_kernel<<<dim3(DD / 256, NG), 256>>>(res1, ids);
    bn_finalize_kernel<<<(AA * DD + 255) / 256, 256>>>();
    bn_apply_kernel<<<(BB * DD / 4) / 256, 256>>>(res1, ids, bng, bnb, norm);

    // FFN (mid reuses g_big, output reuses g_q)
    tgemm(norm, fW1, fb1, big, BB, 2 * DD, DD, ACT_GELU);
    tgemm(big, fW2, fb2, q, BB, DD, 2 * DD, ACT_NONE);
    add_ln_kernel<<<BB, 256>>>(q, norm, ln2g, ln2b, (float*)d_out);
}